// round 14
// baseline (speedup 1.0000x reference)
#include <cuda_runtime.h>
#include <cuda_fp16.h>
#include <cstdint>

// ============================================================================
// NSFPRawMLP: x[262144,3] -> 128 -> (7x 128x128 + ReLU) -> 3
// R14: persistent (148 CTAs, all weights SMEM-resident, zero-sync tile loop)
// + BIAS-AS-INITIAL-ACCUMULATOR (mma D = A*B + bias_frag: kills all C zero-init
// MOVs and all bias adds) + 2-op epilogue (pack, hmax2). Non-MMA instruction
// stream per warp per layer cut ~45%.
// ============================================================================

#define NROWS    262144
#define NHID     7
#define TILE_ROWS 256
#define NTILES   (NROWS / TILE_ROWS)     // 1024 tiles
#define NCTAS    148                     // persistent: one per SM
#define THREADS  256                     // 8 warps, 32 rows/warp

// Weight images: [layer][32768 B] fp16.
// byte = n*256 + ((chunk ^ (n&7))<<4) + (k&7)*2, chunk = k>>3  (XOR swizzle)
static __device__ __align__(128) unsigned char g_wimg[NHID][32768];

// ---------------------------------------------------------------------------
// SMEM layout: 7 weight buffers only (bias via gmem/L1).
// ---------------------------------------------------------------------------
#define SM_WBUF    0                     // 7 x 32768 = 229376
#define SMEM_SZ    229376                // 224 KB

// ---------------------------------------------------------------------------
// PTX helpers (base-target, sm_80+)
// ---------------------------------------------------------------------------
__device__ __forceinline__ uint32_t smem_u32(const void* p) {
    uint32_t a;
    asm("{ .reg .u64 t; cvta.to.shared.u64 t, %1; cvt.u32.u64 %0, t; }"
        : "=r"(a) : "l"(p));
    return a;
}

#define CP_ASYNC16(dst_u32, src_ptr) \
    asm volatile("cp.async.cg.shared.global [%0], [%1], 16;" \
                 :: "r"(dst_u32), "l"(src_ptr) : "memory")
#define CP_COMMIT() asm volatile("cp.async.commit_group;" ::: "memory")
#define CP_WAIT(n)  asm volatile("cp.async.wait_group %0;" :: "n"(n) : "memory")

#define LDSM4(r0, r1, r2, r3, addr) \
    asm volatile("ldmatrix.sync.aligned.m8n8.x4.shared.b16 {%0,%1,%2,%3}, [%4];" \
                 : "=r"(r0), "=r"(r1), "=r"(r2), "=r"(r3) : "r"(addr))

// in-place accumulate: C = A*B + C
#define MMA16816(C, A, b0_, b1_) \
    asm volatile("mma.sync.aligned.m16n8k16.row.col.f32.f16.f16.f32 " \
                 "{%0,%1,%2,%3},{%4,%5,%6,%7},{%8,%9},{%0,%1,%2,%3};" \
                 : "+f"((C)[0]), "+f"((C)[1]), "+f"((C)[2]), "+f"((C)[3]) \
                 : "r"((A)[0]), "r"((A)[1]), "r"((A)[2]), "r"((A)[3]), \
                   "r"(b0_), "r"(b1_))

// init: C = A*B + {bx, by, bx, by}  (bias broadcast across the two row frags)
#define MMA16816_INIT(C, A, b0_, b1_, bx, by) \
    asm volatile("mma.sync.aligned.m16n8k16.row.col.f32.f16.f16.f32 " \
                 "{%0,%1,%2,%3},{%4,%5,%6,%7},{%8,%9},{%10,%11,%10,%11};" \
                 : "=f"((C)[0]), "=f"((C)[1]), "=f"((C)[2]), "=f"((C)[3]) \
                 : "r"((A)[0]), "r"((A)[1]), "r"((A)[2]), "r"((A)[3]), \
                   "r"(b0_), "r"(b1_), "f"(bx), "f"(by))

// pack two fp32 -> fp16x2 (round-to-nearest)
__device__ __forceinline__ uint32_t pack_f16(float v0, float v1) {
    uint32_t r;
    asm("cvt.rn.f16x2.f32 %0, %1, %2;" : "=r"(r) : "f"(v1), "f"(v0));
    return r;
}

__device__ __forceinline__ float relu(float v) { return fmaxf(v, 0.0f); }

// 2-op epilogue: pack (bias already inside C), relu via hmax2 with zero
__device__ __forceinline__ uint32_t epi_op2(float c0, float c1) {
    uint32_t v = pack_f16(c0, c1);
    const __half2 z = __floats2half2_rn(0.f, 0.f);
    __half2 hv = __hmax2(*reinterpret_cast<__half2*>(&v), z);
    return *reinterpret_cast<uint32_t*>(&hv);
}

__device__ __forceinline__ void epi_sg2(uint32_t (&Aout)[4],
                                        const float (&C0)[4], const float (&C1)[4]) {
    Aout[0] = epi_op2(C0[0], C0[1]);
    Aout[1] = epi_op2(C0[2], C0[3]);
    Aout[2] = epi_op2(C1[0], C1[1]);
    Aout[3] = epi_op2(C1[2], C1[3]);
}

// ---------------------------------------------------------------------------
// Prep kernel: Wh fp32 -> fp16 swizzled image.
// ---------------------------------------------------------------------------
__global__ void prep_weights_kernel(const float* __restrict__ Wh) {
    int idx = blockIdx.x * blockDim.x + threadIdx.x;
    if (idx >= NHID * 128 * 128) return;
    int l = idx >> 14;
    int n = (idx >> 7) & 127;
    int k = idx & 127;
    __half w = __float2half_rn(Wh[idx]);
    uint32_t chunk = (uint32_t)k >> 3;
    uint32_t off = (uint32_t)n * 256 + ((chunk ^ ((uint32_t)n & 7)) << 4)
                 + ((uint32_t)k & 7) * 2;
    *(__half*)&g_wimg[l][off] = w;
}

// ---------------------------------------------------------------------------
// One hidden layer: pp-outer k-loop, bias injected via MMA init at s==0,
// per-block epilogue overlapped. No syncs.
// blf: fp32 bias for this layer (gmem, L1-resident after first tile).
// ---------------------------------------------------------------------------
__device__ __forceinline__ void hidden_layer(
    uint32_t wb, const uint32_t (&swz)[8], int q,
    uint32_t (&Aia)[8][4], uint32_t (&Aib)[8][4],
    uint32_t (&Aoa)[8][4], uint32_t (&Aob)[8][4],
    const float* __restrict__ blf) {
    float Ca[16][4], Cb[16][4];
    uint32_t h[2][8];
    LDSM4(h[0][0], h[0][1], h[0][2], h[0][3], wb + swz[0]);
    LDSM4(h[0][4], h[0][5], h[0][6], h[0][7], wb + swz[0] + 4096);
    #pragma unroll
    for (int grp = 0; grp < 32; grp++) {
        const int cur = grp & 1, nxt = cur ^ 1;
        const int pp = grp >> 3, s = grp & 7;
        if (grp + 1 < 32) {
            const int pp1 = (grp + 1) >> 3, s1 = (grp + 1) & 7;
            const uint32_t a0 = wb + swz[s1] + (uint32_t)(2 * pp1) * 4096;
            LDSM4(h[nxt][0], h[nxt][1], h[nxt][2], h[nxt][3], a0);
            LDSM4(h[nxt][4], h[nxt][5], h[nxt][6], h[nxt][7], a0 + 4096);
        }
        if (s == 0) {
            // first k-step: C = A*B + bias (fp32, via MMA accumulator input)
            const float2 bc0 = *(const float2*)&blf[32 * pp + 0 + 2 * q];
            const float2 bc1 = *(const float2*)&blf[32 * pp + 8 + 2 * q];
            const float2 bc2 = *(const float2*)&blf[32 * pp + 16 + 2 * q];
            const float2 bc3 = *(const float2*)&blf[32 * pp + 24 + 2 * q];
            MMA16816_INIT(Ca[4 * pp + 0], Aia[0], h[cur][0], h[cur][1], bc0.x, bc0.y);
            MMA16816_INIT(Cb[4 * pp + 0], Aib[0], h[cur][0], h[cur][1], bc0.x, bc0.y);
            MMA16816_INIT(Ca[4 * pp + 1], Aia[0], h[cur][2], h[cur][3], bc1.x, bc1.y);
            MMA16816_INIT(Cb[4 * pp + 1], Aib[0], h[cur][2], h[cur][3], bc1.x, bc1.y);
            MMA16816_INIT(Ca[4 * pp + 2], Aia[0], h[cur][4], h[cur][5], bc2.x, bc2.y);
            MMA16816_INIT(Cb[4 * pp + 2], Aib[0], h[cur][4], h[cur][5], bc2.x, bc2.y);
            MMA16816_INIT(Ca[4 * pp + 3], Aia[0], h[cur][6], h[cur][7], bc3.x, bc3.y);
            MMA16816_INIT(Cb[4 * pp + 3], Aib[0], h[cur][6], h[cur][7], bc3.x, bc3.y);
        } else {
            MMA16816(Ca[4 * pp + 0], Aia[s], h[cur][0], h[cur][1]);
            MMA16816(Cb[4 * pp + 0], Aib[s], h[cur][0], h[cur][1]);
            MMA16816(Ca[4 * pp + 1], Aia[s], h[cur][2], h[cur][3]);
            MMA16816(Cb[4 * pp + 1], Aib[s], h[cur][2], h[cur][3]);
            MMA16816(Ca[4 * pp + 2], Aia[s], h[cur][4], h[cur][5]);
            MMA16816(Cb[4 * pp + 2], Aib[s], h[cur][4], h[cur][5]);
            MMA16816(Ca[4 * pp + 3], Aia[s], h[cur][6], h[cur][7]);
            MMA16816(Cb[4 * pp + 3], Aib[s], h[cur][6], h[cur][7]);
        }
        // previous block's epilogue (bias already in C): pack + relu only
        if (s == 1 && pp > 0) {
            const int p0 = pp - 1;
            #pragma unroll
            for (int e = 0; e < 2; e++) {
                const int sg = 2 * p0 + e;
                epi_sg2(Aoa[sg], Ca[2 * sg], Ca[2 * sg + 1]);
                epi_sg2(Aob[sg], Cb[2 * sg], Cb[2 * sg + 1]);
            }
        }
    }
    #pragma unroll
    for (int e = 0; e < 2; e++) {
        const int sg = 6 + e;
        epi_sg2(Aoa[sg], Ca[2 * sg], Ca[2 * sg + 1]);
        epi_sg2(Aob[sg], Cb[2 * sg], Cb[2 * sg + 1]);
    }
}

// ---------------------------------------------------------------------------
// Final layer: bias via MMA init; per-block fp32 relu+[128->3] projection.
// ---------------------------------------------------------------------------
__device__ __forceinline__ void final_layer(
    uint32_t wb, const uint32_t (&swz)[8], int q,
    uint32_t (&Aia)[8][4], uint32_t (&Aib)[8][4],
    const float* __restrict__ blf, const float* __restrict__ wout,
    float (&o)[12]) {
    float Ca[16][4], Cb[16][4];
    uint32_t h[2][8];
    LDSM4(h[0][0], h[0][1], h[0][2], h[0][3], wb + swz[0]);
    LDSM4(h[0][4], h[0][5], h[0][6], h[0][7], wb + swz[0] + 4096);
    #pragma unroll
    for (int grp = 0; grp < 32; grp++) {
        const int cur = grp & 1, nxt = cur ^ 1;
        const int pp = grp >> 3, s = grp & 7;
        if (grp + 1 < 32) {
            const int pp1 = (grp + 1) >> 3, s1 = (grp + 1) & 7;
            const uint32_t a0 = wb + swz[s1] + (uint32_t)(2 * pp1) * 4096;
            LDSM4(h[nxt][0], h[nxt][1], h[nxt][2], h[nxt][3], a0);
            LDSM4(h[nxt][4], h[nxt][5], h[nxt][6], h[nxt][7], a0 + 4096);
        }
        if (s == 0) {
            const float2 bc0 = *(const float2*)&blf[32 * pp + 0 + 2 * q];
            const float2 bc1 = *(const float2*)&blf[32 * pp + 8 + 2 * q];
            const float2 bc2 = *(const float2*)&blf[32 * pp + 16 + 2 * q];
            const float2 bc3 = *(const float2*)&blf[32 * pp + 24 + 2 * q];
            MMA16816_INIT(Ca[4 * pp + 0], Aia[0], h[cur][0], h[cur][1], bc0.x, bc0.y);
            MMA16816_INIT(Cb[4 * pp + 0], Aib[0], h[cur][0], h[cur][1], bc0.x, bc0.y);
            MMA16816_INIT(Ca[4 * pp + 1], Aia[0], h[cur][2], h[cur][3], bc1.x, bc1.y);
            MMA16816_INIT(Cb[4 * pp + 1], Aib[0], h[cur][2], h[cur][3], bc1.x, bc1.y);
            MMA16816_INIT(Ca[4 * pp + 2], Aia[0], h[cur][4], h[cur][5], bc2.x, bc2.y);
            MMA16816_INIT(Cb[4 * pp + 2], Aib[0], h[cur][4], h[cur][5], bc2.x, bc2.y);
            MMA16816_INIT(Ca[4 * pp + 3], Aia[0], h[cur][6], h[cur][7], bc3.x, bc3.y);
            MMA16816_INIT(Cb[4 * pp + 3], Aib[0], h[cur][6], h[cur][7], bc3.x, bc3.y);
        } else {
            MMA16816(Ca[4 * pp + 0], Aia[s], h[cur][0], h[cur][1]);
            MMA16816(Cb[4 * pp + 0], Aib[s], h[cur][0], h[cur][1]);
            MMA16816(Ca[4 * pp + 1], Aia[s], h[cur][2], h[cur][3]);
            MMA16816(Cb[4 * pp + 1], Aib[s], h[cur][2], h[cur][3]);
            MMA16816(Ca[4 * pp + 2], Aia[s], h[cur][4], h[cur][5]);
            MMA16816(Cb[4 * pp + 2], Aib[s], h[cur][4], h[cur][5]);
            MMA16816(Ca[4 * pp + 3], Aia[s], h[cur][6], h[cur][7]);
            MMA16816(Cb[4 * pp + 3], Aib[s], h[cur][6], h[cur][7]);
        }
        if (s == 1 && pp > 0) {
            const int p0 = pp - 1;
            #pragma unroll
            for (int g = 4 * p0; g < 4 * p0 + 4; g++) {
                const int c = 8 * g + 2 * q;
                const float2 wj0 = *(const float2*)&wout[0 * 128 + c];
                const float2 wj1 = *(const float2*)&wout[1 * 128 + c];
                const float2 wj2 = *(const float2*)&wout[2 * 128 + c];
                float v00 = relu(Ca[g][0]), v01 = relu(Ca[g][1]);
                float v10 = relu(Ca[g][2]), v11 = relu(Ca[g][3]);
                float v20 = relu(Cb[g][0]), v21 = relu(Cb[g][1]);
                float v30 = relu(Cb[g][2]), v31 = relu(Cb[g][3]);
                o[0]  = fmaf(v00, wj0.x, fmaf(v01, wj0.y, o[0]));
                o[1]  = fmaf(v00, wj1.x, fmaf(v01, wj1.y, o[1]));
                o[2]  = fmaf(v00, wj2.x, fmaf(v01, wj2.y, o[2]));
                o[3]  = fmaf(v10, wj0.x, fmaf(v11, wj0.y, o[3]));
                o[4]  = fmaf(v10, wj1.x, fmaf(v11, wj1.y, o[4]));
                o[5]  = fmaf(v10, wj2.x, fmaf(v11, wj2.y, o[5]));
                o[6]  = fmaf(v20, wj0.x, fmaf(v21, wj0.y, o[6]));
                o[7]  = fmaf(v20, wj1.x, fmaf(v21, wj1.y, o[7]));
                o[8]  = fmaf(v20, wj2.x, fmaf(v21, wj2.y, o[8]));
                o[9]  = fmaf(v30, wj0.x, fmaf(v31, wj0.y, o[9]));
                o[10] = fmaf(v30, wj1.x, fmaf(v31, wj1.y, o[10]));
                o[11] = fmaf(v30, wj2.x, fmaf(v31, wj2.y, o[11]));
            }
        }
    }
    #pragma unroll
    for (int g = 12; g < 16; g++) {
        const int c = 8 * g + 2 * q;
        const float2 wj0 = *(const float2*)&wout[0 * 128 + c];
        const float2 wj1 = *(const float2*)&wout[1 * 128 + c];
        const float2 wj2 = *(const float2*)&wout[2 * 128 + c];
        float v00 = relu(Ca[g][0]), v01 = relu(Ca[g][1]);
        float v10 = relu(Ca[g][2]), v11 = relu(Ca[g][3]);
        float v20 = relu(Cb[g][0]), v21 = relu(Cb[g][1]);
        float v30 = relu(Cb[g][2]), v31 = relu(Cb[g][3]);
        o[0]  = fmaf(v00, wj0.x, fmaf(v01, wj0.y, o[0]));
        o[1]  = fmaf(v00, wj1.x, fmaf(v01, wj1.y, o[1]));
        o[2]  = fmaf(v00, wj2.x, fmaf(v01, wj2.y, o[2]));
        o[3]  = fmaf(v10, wj0.x, fmaf(v11, wj0.y, o[3]));
        o[4]  = fmaf(v10, wj1.x, fmaf(v11, wj1.y, o[4]));
        o[5]  = fmaf(v10, wj2.x, fmaf(v11, wj2.y, o[5]));
        o[6]  = fmaf(v20, wj0.x, fmaf(v21, wj0.y, o[6]));
        o[7]  = fmaf(v20, wj1.x, fmaf(v21, wj1.y, o[7]));
        o[8]  = fmaf(v20, wj2.x, fmaf(v21, wj2.y, o[8]));
        o[9]  = fmaf(v30, wj0.x, fmaf(v31, wj0.y, o[9]));
        o[10] = fmaf(v30, wj1.x, fmaf(v31, wj1.y, o[10]));
        o[11] = fmaf(v30, wj2.x, fmaf(v31, wj2.y, o[11]));
    }
}

// ---------------------------------------------------------------------------
// Main kernel: PERSISTENT. 148 CTAs, 8 warps each, tile-strided over 1024
// tiles of 256 rows. One barrier total; zero syncs in the tile loop.
// ---------------------------------------------------------------------------
__global__ void __launch_bounds__(THREADS, 1)
mlp_kernel(const float* __restrict__ x,
           const float* __restrict__ W0,
           const float* __restrict__ b0,
           const float* __restrict__ bh,
           const float* __restrict__ Wout,
           const float* __restrict__ bout,
           float* __restrict__ out) {
    extern __shared__ char smem[];
    const uint32_t sb = smem_u32(smem);
    const int tid  = threadIdx.x;
    const int wid  = tid >> 5;
    const int lane = tid & 31;
    const int q    = lane & 3;

    // ---- prefetch ALL 7 layer images (once per CTA, ever) ----
    #pragma unroll
    for (int l = 0; l < NHID; l++) {
        const char* src = (const char*)&g_wimg[l][0];
        uint32_t dst = sb + SM_WBUF + (uint32_t)l * 32768;
        #pragma unroll
        for (int i = 0; i < 8; i++)
            CP_ASYNC16(dst + (uint32_t)(tid + i * THREADS) * 16,
                       src + (size_t)(tid + i * THREADS) * 16);
        CP_COMMIT();
    }

    // per-thread ldmatrix address pieces
    const uint32_t nloc = (uint32_t)((lane & 7) + ((lane >> 4) & 1) * 8);
    const uint32_t jbit = (uint32_t)((lane >> 3) & 1);
    uint32_t swz[8];
    #pragma unroll
    for (int s = 0; s < 8; s++)
        swz[s] = nloc * 256 + ((((uint32_t)(2 * s) + jbit) ^ (nloc & 7)) << 4);

    // ---- THE ONLY BARRIER in the entire kernel ----
    CP_WAIT(0);
    __syncthreads();

    uint32_t A0a[8][4], A0b[8][4], A1a[8][4], A1b[8][4];

    // ================= persistent tile loop, zero synchronization ==========
    #pragma unroll 1
    for (int tile = blockIdx.x; tile < NTILES; tile += NCTAS) {
        const int rbase = tile * TILE_ROWS + wid * 32 + (lane >> 2);
        const int g0 = rbase, g1 = rbase + 8, g2 = rbase + 16, g3 = rbase + 24;

        // ---- layer 0: [3 -> 128] fp32 FFMA (W0/b0 via L1) -> fp16 A ----
        {
            const float x00 = x[g0 * 3 + 0], x01 = x[g0 * 3 + 1], x02 = x[g0 * 3 + 2];
            const float x10 = x[g1 * 3 + 0], x11 = x[g1 * 3 + 1], x12 = x[g1 * 3 + 2];
            const float x20 = x[g2 * 3 + 0], x21 = x[g2 * 3 + 1], x22 = x[g2 * 3 + 2];
            const float x30 = x[g3 * 3 + 0], x31 = x[g3 * 3 + 1], x32 = x[g3 * 3 + 2];
            #pragma unroll
            for (int s = 0; s < 8; s++) {
                const int c0 = 16 * s + 2 * q;
                #pragma unroll
                for (int h = 0; h < 2; h++) {
                    const int ca = c0 + 8 * h;
                    const float wa0 = W0[ca * 3 + 0], wa1 = W0[ca * 3 + 1], wa2 = W0[ca * 3 + 2];
                    const float wb0 = W0[(ca + 1) * 3 + 0], wb1 = W0[(ca + 1) * 3 + 1], wb2 = W0[(ca + 1) * 3 + 2];
                    const float ba = b0[ca], bb = b0[ca + 1];
                    float v00 = relu(fmaf(x00, wa0, fmaf(x01, wa1, fmaf(x02, wa2, ba))));
                    float v01 = relu(fmaf(x00, wb0, fmaf(x01, wb1, fmaf(x02, wb2, bb))));
                    float v10 = relu(fmaf(x10, wa0, fmaf(x11, wa1, fmaf(x12, wa2, ba))));
                    float v11 = relu(fmaf(x10, wb0, fmaf(x11, wb1, fmaf(x12, wb2, bb))));
                    A0a[s][2 * h + 0] = pack_f16(v00, v01);
                    A0a[s][2 * h + 1] = pack_f16(v10, v11);
                    float v20 = relu(fmaf(x20, wa0, fmaf(x21, wa1, fmaf(x22, wa2, ba))));
                    float v21 = relu(fmaf(x20, wb0, fmaf(x21, wb1, fmaf(x22, wb2, bb))));
                    float v30 = relu(fmaf(x30, wa0, fmaf(x31, wa1, fmaf(x32, wa2, ba))));
                    float v31 = relu(fmaf(x30, wb0, fmaf(x31, wb1, fmaf(x32, wb2, bb))));
                    A0b[s][2 * h + 0] = pack_f16(v20, v21);
                    A0b[s][2 * h + 1] = pack_f16(v30, v31);
                }
            }
        }

        // ---- 6 hidden layers, no syncs, bias-in-MMA ----
        #pragma unroll 1
        for (int it = 0; it < 3; it++) {
            const int l0 = 2 * it;
            hidden_layer(sb + SM_WBUF + (uint32_t)l0 * 32768, swz, q,
                         A0a, A0b, A1a, A1b, bh + l0 * 128);
            hidden_layer(sb + SM_WBUF + (uint32_t)(l0 + 1) * 32768, swz, q,
                         A1a, A1b, A0a, A0b, bh + (l0 + 1) * 128);
        }

        // ---- final layer (l=6): MMA (+bias) + fused [128->3] projection ----
        float o[12];
        #pragma unroll
        for (int i = 0; i < 12; i++) o[i] = 0.f;
        final_layer(sb + SM_WBUF + 6u * 32768, swz, q, A0a, A0b,
                    bh + 6 * 128, Wout, o);

        #pragma unroll
        for (int d = 1; d <= 2; d <<= 1) {
            #pragma unroll
            for (int i = 0; i < 12; i++)
                o[i] += __shfl_xor_sync(0xFFFFFFFF, o[i], d);
        }
        if (q == 0) {
            const float bo0 = bout[0], bo1 = bout[1], bo2 = bout[2];
            out[g0 * 3 + 0] = o[0] + bo0;
            out[g0 * 3 + 1] = o[1] + bo1;
            out[g0 * 3 + 2] = o[2] + bo2;
            out[g1 * 3 + 0] = o[3] + bo0;
            out[g1 * 3 + 1] = o[4] + bo1;
            out[g1 * 3 + 2] = o[5] + bo2;
            out[g2 * 3 + 0] = o[6] + bo0;
            out[g2 * 3 + 1] = o[7] + bo1;
            out[g2 * 3 + 2] = o[8] + bo2;
            out[g3 * 3 + 0] = o[9] + bo0;
            out[g3 * 3 + 1] = o[10] + bo1;
            out[g3 * 3 + 2] = o[11] + bo2;
        }
    }
}

// ---------------------------------------------------------------------------
// kernel_launch
// ---------------------------------------------------------------------------
extern "C" void kernel_launch(void* const* d_in, const int* in_sizes, int n_in,
                              void* d_out, int out_size) {
    const float* x    = (const float*)d_in[0];   // [262144,3]
    const float* W0   = (const float*)d_in[1];   // [128,3]
    const float* b0   = (const float*)d_in[2];   // [128]
    const float* Wh   = (const float*)d_in[3];   // [7,128,128]
    const float* bh   = (const float*)d_in[4];   // [7,128]
    const float* Wout = (const float*)d_in[5];   // [3,128]
    const float* bout = (const float*)d_in[6];   // [3]
    float* out = (float*)d_out;                  // [262144,3]

    static bool attr_set = false;
    if (!attr_set) {
        cudaFuncSetAttribute(mlp_kernel,
                             cudaFuncAttributeMaxDynamicSharedMemorySize, SMEM_SZ);
        attr_set = true;
    }

    prep_weights_kernel<<<(NHID * 128 * 128 + 255) / 256, 256>>>(Wh);
    mlp_kernel<<<NCTAS, THREADS, SMEM_SZ>>>(x, W0, b0, bh, Wout, bout, out);
}

// round 15
// speedup vs baseline: 1.0492x; 1.0492x over previous
#include <cuda_runtime.h>
#include <cuda_fp16.h>
#include <cstdint>

// ============================================================================
// NSFPRawMLP: x[262144,3] -> 128 -> (7x 128x128 + ReLU) -> 3
// R15: R12 persistent base (148 CTAs, all weights SMEM-resident, zero-sync
// tile loop, f16x2 smem bias epilogue) +
//   (a) final 128->3 projection as m16n8k8 MMAs (no shuffles/FMAs), layer 6
//       handled by the regular hidden_layer epilogue,
//   (b) next-tile x prefetched behind the 7-layer MMA stream.
// ============================================================================

#define NROWS    262144
#define NHID     7
#define TILE_ROWS 256
#define NTILES   (NROWS / TILE_ROWS)     // 1024 tiles
#define NCTAS    148                     // persistent: one per SM
#define THREADS  256                     // 8 warps, 32 rows/warp

// Weight images: [layer][32768 B] fp16.
// byte = n*256 + ((chunk ^ (n&7))<<4) + (k&7)*2, chunk = k>>3  (XOR swizzle)
static __device__ __align__(128) unsigned char g_wimg[NHID][32768];
// Wout fragment stream for m16n8k8: [16 k8-chunks][12 lanes] packed f16x2
static __device__ uint32_t g_woutfrag[192];

// ---------------------------------------------------------------------------
// SMEM layout
// ---------------------------------------------------------------------------
#define SM_WBUF    0                     // 7 x 32768 = 229376
#define SM_BIASH   229376                // 7*64 half2 = 1792
#define SM_WOUTF   231168                // 192 words = 768
#define SMEM_SZ    231936

// ---------------------------------------------------------------------------
// PTX helpers (base-target, sm_80+)
// ---------------------------------------------------------------------------
__device__ __forceinline__ uint32_t smem_u32(const void* p) {
    uint32_t a;
    asm("{ .reg .u64 t; cvta.to.shared.u64 t, %1; cvt.u32.u64 %0, t; }"
        : "=r"(a) : "l"(p));
    return a;
}

#define CP_ASYNC16(dst_u32, src_ptr) \
    asm volatile("cp.async.cg.shared.global [%0], [%1], 16;" \
                 :: "r"(dst_u32), "l"(src_ptr) : "memory")
#define CP_COMMIT() asm volatile("cp.async.commit_group;" ::: "memory")
#define CP_WAIT(n)  asm volatile("cp.async.wait_group %0;" :: "n"(n) : "memory")

#define LDSM4(r0, r1, r2, r3, addr) \
    asm volatile("ldmatrix.sync.aligned.m8n8.x4.shared.b16 {%0,%1,%2,%3}, [%4];" \
                 : "=r"(r0), "=r"(r1), "=r"(r2), "=r"(r3) : "r"(addr))

#define MMA16816(C, A, b0_, b1_) \
    asm volatile("mma.sync.aligned.m16n8k16.row.col.f32.f16.f16.f32 " \
                 "{%0,%1,%2,%3},{%4,%5,%6,%7},{%8,%9},{%0,%1,%2,%3};" \
                 : "+f"((C)[0]), "+f"((C)[1]), "+f"((C)[2]), "+f"((C)[3]) \
                 : "r"((A)[0]), "r"((A)[1]), "r"((A)[2]), "r"((A)[3]), \
                   "r"(b0_), "r"(b1_))

// k8 MMA for the tiny output projection
#define MMA16808(C, a0_, a1_, b_) \
    asm volatile("mma.sync.aligned.m16n8k8.row.col.f32.f16.f16.f32 " \
                 "{%0,%1,%2,%3},{%4,%5},{%6},{%0,%1,%2,%3};" \
                 : "+f"((C)[0]), "+f"((C)[1]), "+f"((C)[2]), "+f"((C)[3]) \
                 : "r"(a0_), "r"(a1_), "r"(b_))

#define MMA16808_INIT(C, a0_, a1_, b_, bx, by) \
    asm volatile("mma.sync.aligned.m16n8k8.row.col.f32.f16.f16.f32 " \
                 "{%0,%1,%2,%3},{%4,%5},{%6},{%7,%8,%7,%8};" \
                 : "=f"((C)[0]), "=f"((C)[1]), "=f"((C)[2]), "=f"((C)[3]) \
                 : "r"(a0_), "r"(a1_), "r"(b_), "f"(bx), "f"(by))

// pack two fp32 -> fp16x2 (round-to-nearest)
__device__ __forceinline__ uint32_t pack_f16(float v0, float v1) {
    uint32_t r;
    asm("cvt.rn.f16x2.f32 %0, %1, %2;" : "=r"(r) : "f"(v1), "f"(v0));
    return r;
}

__device__ __forceinline__ float relu(float v) { return fmaxf(v, 0.0f); }

// f16x2 epilogue op: pack(c0,c1) + bias2 (f16), relu via hmax2
__device__ __forceinline__ uint32_t epi_op(float c0, float c1, uint32_t b2) {
    uint32_t v = pack_f16(c0, c1);
    __half2 hv = __hadd2(*reinterpret_cast<__half2*>(&v),
                         *reinterpret_cast<const __half2*>(&b2));
    const __half2 z = __floats2half2_rn(0.f, 0.f);
    hv = __hmax2(hv, z);
    return *reinterpret_cast<uint32_t*>(&hv);
}

__device__ __forceinline__ void epi_sg(uint32_t (&Aout)[4],
                                       const float (&C0)[4], const float (&C1)[4],
                                       uint32_t b20, uint32_t b21) {
    Aout[0] = epi_op(C0[0], C0[1], b20);
    Aout[1] = epi_op(C0[2], C0[3], b20);
    Aout[2] = epi_op(C1[0], C1[1], b21);
    Aout[3] = epi_op(C1[2], C1[3], b21);
}

// ---------------------------------------------------------------------------
// Prep kernels
// ---------------------------------------------------------------------------
__global__ void prep_weights_kernel(const float* __restrict__ Wh) {
    int idx = blockIdx.x * blockDim.x + threadIdx.x;
    if (idx >= NHID * 128 * 128) return;
    int l = idx >> 14;
    int n = (idx >> 7) & 127;
    int k = idx & 127;
    __half w = __float2half_rn(Wh[idx]);
    uint32_t chunk = (uint32_t)k >> 3;
    uint32_t off = (uint32_t)n * 256 + ((chunk ^ ((uint32_t)n & 7)) << 4)
                 + ((uint32_t)k & 7) * 2;
    *(__half*)&g_wimg[l][off] = w;
}

// Wout frag stream: word[c*12 + l], l -> (n = l>>2, q = l&3), k = 8c+2q
__global__ void prep_wout_kernel(const float* __restrict__ Wout) {
    int idx = threadIdx.x;
    if (idx >= 192) return;
    int c = idx / 12, l = idx % 12;
    int n = l >> 2, qq = l & 3;
    int k0 = 8 * c + 2 * qq;
    g_woutfrag[idx] = pack_f16(Wout[n * 128 + k0], Wout[n * 128 + k0 + 1]);
}

// ---------------------------------------------------------------------------
// One hidden layer: pp-outer k-loop, per-block epilogue overlapped. No syncs.
// ---------------------------------------------------------------------------
__device__ __forceinline__ void hidden_layer(
    uint32_t wb, const uint32_t (&swz)[8], int q,
    uint32_t (&Aia)[8][4], uint32_t (&Aib)[8][4],
    uint32_t (&Aoa)[8][4], uint32_t (&Aob)[8][4],
    const uint32_t* __restrict__ b2) {
    float Ca[16][4], Cb[16][4];
    uint32_t h[2][8];
    LDSM4(h[0][0], h[0][1], h[0][2], h[0][3], wb + swz[0]);
    LDSM4(h[0][4], h[0][5], h[0][6], h[0][7], wb + swz[0] + 4096);
    #pragma unroll
    for (int grp = 0; grp < 32; grp++) {
        const int cur = grp & 1, nxt = cur ^ 1;
        const int pp = grp >> 3, s = grp & 7;
        if (grp + 1 < 32) {
            const int pp1 = (grp + 1) >> 3, s1 = (grp + 1) & 7;
            const uint32_t a0 = wb + swz[s1] + (uint32_t)(2 * pp1) * 4096;
            LDSM4(h[nxt][0], h[nxt][1], h[nxt][2], h[nxt][3], a0);
            LDSM4(h[nxt][4], h[nxt][5], h[nxt][6], h[nxt][7], a0 + 4096);
        }
        if (s == 0) {
            #pragma unroll
            for (int j = 0; j < 4; j++) {
                Ca[4 * pp + j][0] = 0.f; Ca[4 * pp + j][1] = 0.f;
                Ca[4 * pp + j][2] = 0.f; Ca[4 * pp + j][3] = 0.f;
                Cb[4 * pp + j][0] = 0.f; Cb[4 * pp + j][1] = 0.f;
                Cb[4 * pp + j][2] = 0.f; Cb[4 * pp + j][3] = 0.f;
            }
        }
        MMA16816(Ca[4 * pp + 0], Aia[s], h[cur][0], h[cur][1]);
        MMA16816(Cb[4 * pp + 0], Aib[s], h[cur][0], h[cur][1]);
        MMA16816(Ca[4 * pp + 1], Aia[s], h[cur][2], h[cur][3]);
        MMA16816(Cb[4 * pp + 1], Aib[s], h[cur][2], h[cur][3]);
        MMA16816(Ca[4 * pp + 2], Aia[s], h[cur][4], h[cur][5]);
        MMA16816(Cb[4 * pp + 2], Aib[s], h[cur][4], h[cur][5]);
        MMA16816(Ca[4 * pp + 3], Aia[s], h[cur][6], h[cur][7]);
        MMA16816(Cb[4 * pp + 3], Aib[s], h[cur][6], h[cur][7]);
        if (s == 1 && pp > 0) {
            const int p0 = pp - 1;
            #pragma unroll
            for (int e = 0; e < 2; e++) {
                const int sg = 2 * p0 + e;
                const uint32_t b20 = b2[8 * sg + q];
                const uint32_t b21 = b2[8 * sg + 4 + q];
                epi_sg(Aoa[sg], Ca[2 * sg], Ca[2 * sg + 1], b20, b21);
                epi_sg(Aob[sg], Cb[2 * sg], Cb[2 * sg + 1], b20, b21);
            }
        }
    }
    #pragma unroll
    for (int e = 0; e < 2; e++) {
        const int sg = 6 + e;
        const uint32_t b20 = b2[8 * sg + q];
        const uint32_t b21 = b2[8 * sg + 4 + q];
        epi_sg(Aoa[sg], Ca[2 * sg], Ca[2 * sg + 1], b20, b21);
        epi_sg(Aob[sg], Cb[2 * sg], Cb[2 * sg + 1], b20, b21);
    }
}

// ---------------------------------------------------------------------------
// Main kernel: PERSISTENT. 148 CTAs, 8 warps each, tile-strided over 1024
// tiles of 256 rows. One barrier total; zero syncs in the tile loop.
// ---------------------------------------------------------------------------
__global__ void __launch_bounds__(THREADS, 1)
mlp_kernel(const float* __restrict__ x,
           const float* __restrict__ W0,
           const float* __restrict__ b0,
           const float* __restrict__ bh,
           const float* __restrict__ Wout,
           const float* __restrict__ bout,
           float* __restrict__ out) {
    extern __shared__ char smem[];
    const uint32_t sb = smem_u32(smem);
    const int tid  = threadIdx.x;
    const int wid  = tid >> 5;
    const int lane = tid & 31;
    const int q    = lane & 3;

    // ---- prefetch ALL 7 layer images (once per CTA, ever) ----
    #pragma unroll
    for (int l = 0; l < NHID; l++) {
        const char* src = (const char*)&g_wimg[l][0];
        uint32_t dst = sb + SM_WBUF + (uint32_t)l * 32768;
        #pragma unroll
        for (int i = 0; i < 8; i++)
            CP_ASYNC16(dst + (uint32_t)(tid + i * THREADS) * 16,
                       src + (size_t)(tid + i * THREADS) * 16);
        CP_COMMIT();
    }

    // ---- stage f16x2 biases + Wout frag stream ----
    {
        uint32_t* b2s = (uint32_t*)(smem + SM_BIASH);
        for (int i = tid; i < NHID * 64; i += THREADS)
            b2s[i] = pack_f16(bh[2 * i], bh[2 * i + 1]);
        if (tid < 192)
            ((uint32_t*)(smem + SM_WOUTF))[tid] = g_woutfrag[tid];
    }

    // per-thread ldmatrix address pieces
    const uint32_t nloc = (uint32_t)((lane & 7) + ((lane >> 4) & 1) * 8);
    const uint32_t jbit = (uint32_t)((lane >> 3) & 1);
    uint32_t swz[8];
    #pragma unroll
    for (int s = 0; s < 8; s++)
        swz[s] = nloc * 256 + ((((uint32_t)(2 * s) + jbit) ^ (nloc & 7)) << 4);

    const uint32_t* b2base = (const uint32_t*)(smem + SM_BIASH);
    const uint32_t* wf = (const uint32_t*)(smem + SM_WOUTF);

    // final-projection bias pattern (cols 2q, 2q+1 of [bout0,bout1,bout2,0])
    float bfx = 0.f, bfy = 0.f;
    if (q == 0) { bfx = bout[0]; bfy = bout[1]; }
    else if (q == 1) { bfx = bout[2]; }

    // ---- THE ONLY BARRIER in the entire kernel ----
    CP_WAIT(0);
    __syncthreads();

    uint32_t A0a[8][4], A0b[8][4], A1a[8][4], A1b[8][4];

    // x for the first tile
    float xc[12];
    {
        const int r = blockIdx.x * TILE_ROWS + wid * 32 + (lane >> 2);
        const float* xp = x + (size_t)r * 3;
        #pragma unroll
        for (int j = 0; j < 4; j++) {
            xc[3 * j + 0] = xp[24 * j + 0];
            xc[3 * j + 1] = xp[24 * j + 1];
            xc[3 * j + 2] = xp[24 * j + 2];
        }
    }

    // ================= persistent tile loop, zero synchronization ==========
    #pragma unroll 1
    for (int tile = blockIdx.x; tile < NTILES; tile += NCTAS) {
        const int rbase = tile * TILE_ROWS + wid * 32 + (lane >> 2);
        const int g0 = rbase, g1 = rbase + 8, g2 = rbase + 16, g3 = rbase + 24;

        // ---- layer 0: [3 -> 128] fp32 FFMA (W0/b0 via L1) -> fp16 A ----
        {
            #pragma unroll
            for (int s = 0; s < 8; s++) {
                const int c0 = 16 * s + 2 * q;
                #pragma unroll
                for (int h = 0; h < 2; h++) {
                    const int ca = c0 + 8 * h;
                    const float wa0 = W0[ca * 3 + 0], wa1 = W0[ca * 3 + 1], wa2 = W0[ca * 3 + 2];
                    const float wb0 = W0[(ca + 1) * 3 + 0], wb1 = W0[(ca + 1) * 3 + 1], wb2 = W0[(ca + 1) * 3 + 2];
                    const float ba = b0[ca], bb = b0[ca + 1];
                    float v00 = relu(fmaf(xc[0], wa0, fmaf(xc[1], wa1, fmaf(xc[2], wa2, ba))));
                    float v01 = relu(fmaf(xc[0], wb0, fmaf(xc[1], wb1, fmaf(xc[2], wb2, bb))));
                    float v10 = relu(fmaf(xc[3], wa0, fmaf(xc[4], wa1, fmaf(xc[5], wa2, ba))));
                    float v11 = relu(fmaf(xc[3], wb0, fmaf(xc[4], wb1, fmaf(xc[5], wb2, bb))));
                    A0a[s][2 * h + 0] = pack_f16(v00, v01);
                    A0a[s][2 * h + 1] = pack_f16(v10, v11);
                    float v20 = relu(fmaf(xc[6], wa0, fmaf(xc[7], wa1, fmaf(xc[8], wa2, ba))));
                    float v21 = relu(fmaf(xc[6], wb0, fmaf(xc[7], wb1, fmaf(xc[8], wb2, bb))));
                    float v30 = relu(fmaf(xc[9], wa0, fmaf(xc[10], wa1, fmaf(xc[11], wa2, ba))));
                    float v31 = relu(fmaf(xc[9], wb0, fmaf(xc[10], wb1, fmaf(xc[11], wb2, bb))));
                    A0b[s][2 * h + 0] = pack_f16(v20, v21);
                    A0b[s][2 * h + 1] = pack_f16(v30, v31);
                }
            }
        }

        // ---- prefetch next tile's x (latency hidden behind 7 MMA layers) ----
        {
            const int ntile = tile + NCTAS;
            if (ntile < NTILES) {
                const int r = ntile * TILE_ROWS + wid * 32 + (lane >> 2);
                const float* xp = x + (size_t)r * 3;
                #pragma unroll
                for (int j = 0; j < 4; j++) {
                    xc[3 * j + 0] = xp[24 * j + 0];
                    xc[3 * j + 1] = xp[24 * j + 1];
                    xc[3 * j + 2] = xp[24 * j + 2];
                }
            }
        }

        // ---- 6 hidden layers, no syncs ----
        #pragma unroll 1
        for (int it = 0; it < 3; it++) {
            const int l0 = 2 * it;
            hidden_layer(sb + SM_WBUF + (uint32_t)l0 * 32768, swz, q,
                         A0a, A0b, A1a, A1b, b2base + l0 * 64);
            hidden_layer(sb + SM_WBUF + (uint32_t)(l0 + 1) * 32768, swz, q,
                         A1a, A1b, A0a, A0b, b2base + (l0 + 1) * 64);
        }
        // ---- hidden layer 6 (A0 -> A1 = relu(h7) fp16 frags) ----
        hidden_layer(sb + SM_WBUF + 6u * 32768, swz, q,
                     A0a, A0b, A1a, A1b, b2base + 6 * 64);

        // ---- final [128 -> 3] projection via m16n8k8 MMAs ----
        {
            float Cfa[4], Cfb[4];
            {
                const uint32_t bw = (lane < 12) ? wf[lane] : 0u;
                MMA16808_INIT(Cfa, A1a[0][0], A1a[0][1], bw, bfx, bfy);
                MMA16808_INIT(Cfb, A1b[0][0], A1b[0][1], bw, bfx, bfy);
            }
            #pragma unroll
            for (int c = 1; c < 16; c++) {
                const uint32_t bw = (lane < 12) ? wf[c * 12 + lane] : 0u;
                const int s = c >> 1, off = (c & 1) * 2;
                MMA16808(Cfa, A1a[s][off], A1a[s][off + 1], bw);
                MMA16808(Cfb, A1b[s][off], A1b[s][off + 1], bw);
            }
            if (q == 0) {
                out[g0 * 3 + 0] = Cfa[0]; out[g0 * 3 + 1] = Cfa[1];
                out[g1 * 3 + 0] = Cfa[2]; out[g1 * 3 + 1] = Cfa[3];
                out[g2 * 3 + 0] = Cfb[0]; out[g2 * 3 + 1] = Cfb[1];
                out[g3 * 3 + 0] = Cfb[2]; out[g3 * 3 + 1] = Cfb[3];
            } else if (q == 1) {
                out[g0 * 3 + 2] = Cfa[0]; out[g1 * 3 + 2] = Cfa[2];
                out[g2 * 3 + 2] = Cfb[0]; out[g3 * 3 + 2] = Cfb[2];
            }
        }
    }
}

// ---------------------------------------------------------------------------
// kernel_launch
// ---------------------------------------------------------------------------
extern "C" void kernel_launch(void* const* d_in, const int* in_sizes, int n_in,
                              void* d_out, int out_size) {
    const float* x    = (const float*)d_in[0];   // [262144,3]
    const float* W0   = (const float*)d_in[1];   // [128,3]
    const float* b0   = (const float*)d_in[2];   // [128]
    const float* Wh   = (const float*)d_in[3];   // [7,128,128]
    const float* bh   = (const float*)d_in[4];   // [7,128]
    const float* Wout = (const float*)d_in[5];   // [3,128]
    const float* bout = (const float*)d_in[6];   // [3]
    float* out = (float*)d_out;                  // [262144,3]

    static bool attr_set = false;
    if (!attr_set) {
        cudaFuncSetAttribute(mlp_kernel,
                             cudaFuncAttributeMaxDynamicSharedMemorySize, SMEM_SZ);
        attr_set = true;
    }

    prep_weights_kernel<<<(NHID * 128 * 128 + 255) / 256, 256>>>(Wh);
    prep_wout_kernel<<<1, 192>>>(Wout);
    mlp_kernel<<<NCTAS, THREADS, SMEM_SZ>>>(x, W0, b0, bh, Wout, bout, out);
}

// round 16
// speedup vs baseline: 1.0703x; 1.0201x over previous
#include <cuda_runtime.h>
#include <cuda_fp16.h>
#include <cstdint>

// ============================================================================
// NSFPRawMLP: x[262144,3] -> 128 -> (7x 128x128 + ReLU) -> 3
// R16: R15 persistent base (148 CTAs, all weights SMEM-resident, zero-sync
// tile loop, MMA-ized 128->3 projection, x prefetch) +
//   LAYER 0 VIA m16n8k8 MMA: x padded to K=8 with bias in k=3 of a
//   precomputed [W0|b0] fp16 frag table (global, L1-hot). Kills ~200 serial
//   FFMA/relu/pack issues per warp per tile.
// ============================================================================

#define NROWS    262144
#define NHID     7
#define TILE_ROWS 256
#define NTILES   (NROWS / TILE_ROWS)     // 1024 tiles
#define NCTAS    148                     // persistent: one per SM
#define THREADS  256                     // 8 warps, 32 rows/warp

// Weight images: [layer][32768 B] fp16.
// byte = n*256 + ((chunk ^ (n&7))<<4) + (k&7)*2, chunk = k>>3  (XOR swizzle)
static __device__ __align__(128) unsigned char g_wimg[NHID][32768];
// Wout fragment stream for m16n8k8: [16 k8-chunks][12 lanes] packed f16x2
static __device__ uint32_t g_woutfrag[192];
// [W0 | b0] fragment table for layer-0 m16n8k8: [16 n-tiles][32 lanes]
static __device__ uint32_t g_w0frag[512];

// ---------------------------------------------------------------------------
// SMEM layout
// ---------------------------------------------------------------------------
#define SM_WBUF    0                     // 7 x 32768 = 229376
#define SM_BIASH   229376                // 7*64 half2 = 1792
#define SM_WOUTF   231168                // 192 words = 768
#define SMEM_SZ    231936

// ---------------------------------------------------------------------------
// PTX helpers (base-target, sm_80+)
// ---------------------------------------------------------------------------
__device__ __forceinline__ uint32_t smem_u32(const void* p) {
    uint32_t a;
    asm("{ .reg .u64 t; cvta.to.shared.u64 t, %1; cvt.u32.u64 %0, t; }"
        : "=r"(a) : "l"(p));
    return a;
}

#define CP_ASYNC16(dst_u32, src_ptr) \
    asm volatile("cp.async.cg.shared.global [%0], [%1], 16;" \
                 :: "r"(dst_u32), "l"(src_ptr) : "memory")
#define CP_COMMIT() asm volatile("cp.async.commit_group;" ::: "memory")
#define CP_WAIT(n)  asm volatile("cp.async.wait_group %0;" :: "n"(n) : "memory")

#define LDSM4(r0, r1, r2, r3, addr) \
    asm volatile("ldmatrix.sync.aligned.m8n8.x4.shared.b16 {%0,%1,%2,%3}, [%4];" \
                 : "=r"(r0), "=r"(r1), "=r"(r2), "=r"(r3) : "r"(addr))

#define MMA16816(C, A, b0_, b1_) \
    asm volatile("mma.sync.aligned.m16n8k16.row.col.f32.f16.f16.f32 " \
                 "{%0,%1,%2,%3},{%4,%5,%6,%7},{%8,%9},{%0,%1,%2,%3};" \
                 : "+f"((C)[0]), "+f"((C)[1]), "+f"((C)[2]), "+f"((C)[3]) \
                 : "r"((A)[0]), "r"((A)[1]), "r"((A)[2]), "r"((A)[3]), \
                   "r"(b0_), "r"(b1_))

// k8 MMA (used for layer 0 and the output projection)
#define MMA16808(C, a0_, a1_, b_) \
    asm volatile("mma.sync.aligned.m16n8k8.row.col.f32.f16.f16.f32 " \
                 "{%0,%1,%2,%3},{%4,%5},{%6},{%0,%1,%2,%3};" \
                 : "+f"((C)[0]), "+f"((C)[1]), "+f"((C)[2]), "+f"((C)[3]) \
                 : "r"(a0_), "r"(a1_), "r"(b_))

#define MMA16808_INIT(C, a0_, a1_, b_, bx, by) \
    asm volatile("mma.sync.aligned.m16n8k8.row.col.f32.f16.f16.f32 " \
                 "{%0,%1,%2,%3},{%4,%5},{%6},{%7,%8,%7,%8};" \
                 : "=f"((C)[0]), "=f"((C)[1]), "=f"((C)[2]), "=f"((C)[3]) \
                 : "r"(a0_), "r"(a1_), "r"(b_), "f"(bx), "f"(by))

// pack two fp32 -> fp16x2 (round-to-nearest)
__device__ __forceinline__ uint32_t pack_f16(float v0, float v1) {
    uint32_t r;
    asm("cvt.rn.f16x2.f32 %0, %1, %2;" : "=r"(r) : "f"(v1), "f"(v0));
    return r;
}

__device__ __forceinline__ float relu(float v) { return fmaxf(v, 0.0f); }

// f16x2 epilogue op: pack(c0,c1) + bias2 (f16), relu via hmax2
__device__ __forceinline__ uint32_t epi_op(float c0, float c1, uint32_t b2) {
    uint32_t v = pack_f16(c0, c1);
    __half2 hv = __hadd2(*reinterpret_cast<__half2*>(&v),
                         *reinterpret_cast<const __half2*>(&b2));
    const __half2 z = __floats2half2_rn(0.f, 0.f);
    hv = __hmax2(hv, z);
    return *reinterpret_cast<uint32_t*>(&hv);
}

// 2-op epilogue (bias already in C): pack + relu via hmax2
__device__ __forceinline__ uint32_t epi_op2(float c0, float c1) {
    uint32_t v = pack_f16(c0, c1);
    const __half2 z = __floats2half2_rn(0.f, 0.f);
    __half2 hv = __hmax2(*reinterpret_cast<__half2*>(&v), z);
    return *reinterpret_cast<uint32_t*>(&hv);
}

__device__ __forceinline__ void epi_sg(uint32_t (&Aout)[4],
                                       const float (&C0)[4], const float (&C1)[4],
                                       uint32_t b20, uint32_t b21) {
    Aout[0] = epi_op(C0[0], C0[1], b20);
    Aout[1] = epi_op(C0[2], C0[3], b20);
    Aout[2] = epi_op(C1[0], C1[1], b21);
    Aout[3] = epi_op(C1[2], C1[3], b21);
}

// layer-0 x fragment: padded row [x0,x1,x2,1,0,0,0,0], cols 2q,2q+1
__device__ __forceinline__ uint32_t xfrag(float x0, float x1, float x2, int q) {
    float u0 = (q == 0) ? x0 : (q == 1 ? x2 : 0.f);
    float u1 = (q == 0) ? x1 : (q == 1 ? 1.0f : 0.f);
    return pack_f16(u0, u1);
}

// ---------------------------------------------------------------------------
// Prep kernels
// ---------------------------------------------------------------------------
__global__ void prep_weights_kernel(const float* __restrict__ Wh) {
    int idx = blockIdx.x * blockDim.x + threadIdx.x;
    if (idx >= NHID * 128 * 128) return;
    int l = idx >> 14;
    int n = (idx >> 7) & 127;
    int k = idx & 127;
    __half w = __float2half_rn(Wh[idx]);
    uint32_t chunk = (uint32_t)k >> 3;
    uint32_t off = (uint32_t)n * 256 + ((chunk ^ ((uint32_t)n & 7)) << 4)
                 + ((uint32_t)k & 7) * 2;
    *(__half*)&g_wimg[l][off] = w;
}

// Wout frag stream + [W0|b0] frag table
__global__ void prep_small_kernel(const float* __restrict__ Wout,
                                  const float* __restrict__ W0,
                                  const float* __restrict__ b0) {
    int idx = threadIdx.x;
    if (idx < 192) {
        int c = idx / 12, l = idx % 12;
        int n = l >> 2, qq = l & 3;
        int k0 = 8 * c + 2 * qq;
        g_woutfrag[idx] = pack_f16(Wout[n * 128 + k0], Wout[n * 128 + k0 + 1]);
    }
    if (idx < 512) {
        int c = idx >> 5, l = idx & 31;
        int n = c * 8 + (l >> 2);
        int qq = l & 3;
        int k0 = 2 * qq, k1 = 2 * qq + 1;
        float v0 = (k0 < 3) ? W0[n * 3 + k0] : ((k0 == 3) ? b0[n] : 0.f);
        float v1 = (k1 < 3) ? W0[n * 3 + k1] : ((k1 == 3) ? b0[n] : 0.f);
        g_w0frag[idx] = pack_f16(v0, v1);
    }
}

// ---------------------------------------------------------------------------
// One hidden layer: pp-outer k-loop, per-block epilogue overlapped. No syncs.
// ---------------------------------------------------------------------------
__device__ __forceinline__ void hidden_layer(
    uint32_t wb, const uint32_t (&swz)[8], int q,
    uint32_t (&Aia)[8][4], uint32_t (&Aib)[8][4],
    uint32_t (&Aoa)[8][4], uint32_t (&Aob)[8][4],
    const uint32_t* __restrict__ b2) {
    float Ca[16][4], Cb[16][4];
    uint32_t h[2][8];
    LDSM4(h[0][0], h[0][1], h[0][2], h[0][3], wb + swz[0]);
    LDSM4(h[0][4], h[0][5], h[0][6], h[0][7], wb + swz[0] + 4096);
    #pragma unroll
    for (int grp = 0; grp < 32; grp++) {
        const int cur = grp & 1, nxt = cur ^ 1;
        const int pp = grp >> 3, s = grp & 7;
        if (grp + 1 < 32) {
            const int pp1 = (grp + 1) >> 3, s1 = (grp + 1) & 7;
            const uint32_t a0 = wb + swz[s1] + (uint32_t)(2 * pp1) * 4096;
            LDSM4(h[nxt][0], h[nxt][1], h[nxt][2], h[nxt][3], a0);
            LDSM4(h[nxt][4], h[nxt][5], h[nxt][6], h[nxt][7], a0 + 4096);
        }
        if (s == 0) {
            #pragma unroll
            for (int j = 0; j < 4; j++) {
                Ca[4 * pp + j][0] = 0.f; Ca[4 * pp + j][1] = 0.f;
                Ca[4 * pp + j][2] = 0.f; Ca[4 * pp + j][3] = 0.f;
                Cb[4 * pp + j][0] = 0.f; Cb[4 * pp + j][1] = 0.f;
                Cb[4 * pp + j][2] = 0.f; Cb[4 * pp + j][3] = 0.f;
            }
        }
        MMA16816(Ca[4 * pp + 0], Aia[s], h[cur][0], h[cur][1]);
        MMA16816(Cb[4 * pp + 0], Aib[s], h[cur][0], h[cur][1]);
        MMA16816(Ca[4 * pp + 1], Aia[s], h[cur][2], h[cur][3]);
        MMA16816(Cb[4 * pp + 1], Aib[s], h[cur][2], h[cur][3]);
        MMA16816(Ca[4 * pp + 2], Aia[s], h[cur][4], h[cur][5]);
        MMA16816(Cb[4 * pp + 2], Aib[s], h[cur][4], h[cur][5]);
        MMA16816(Ca[4 * pp + 3], Aia[s], h[cur][6], h[cur][7]);
        MMA16816(Cb[4 * pp + 3], Aib[s], h[cur][6], h[cur][7]);
        if (s == 1 && pp > 0) {
            const int p0 = pp - 1;
            #pragma unroll
            for (int e = 0; e < 2; e++) {
                const int sg = 2 * p0 + e;
                const uint32_t b20 = b2[8 * sg + q];
                const uint32_t b21 = b2[8 * sg + 4 + q];
                epi_sg(Aoa[sg], Ca[2 * sg], Ca[2 * sg + 1], b20, b21);
                epi_sg(Aob[sg], Cb[2 * sg], Cb[2 * sg + 1], b20, b21);
            }
        }
    }
    #pragma unroll
    for (int e = 0; e < 2; e++) {
        const int sg = 6 + e;
        const uint32_t b20 = b2[8 * sg + q];
        const uint32_t b21 = b2[8 * sg + 4 + q];
        epi_sg(Aoa[sg], Ca[2 * sg], Ca[2 * sg + 1], b20, b21);
        epi_sg(Aob[sg], Cb[2 * sg], Cb[2 * sg + 1], b20, b21);
    }
}

// ---------------------------------------------------------------------------
// Main kernel: PERSISTENT. 148 CTAs, 8 warps each, tile-strided over 1024
// tiles of 256 rows. One barrier total; zero syncs in the tile loop.
// ---------------------------------------------------------------------------
__global__ void __launch_bounds__(THREADS, 1)
mlp_kernel(const float* __restrict__ x,
           const float* __restrict__ W0,
           const float* __restrict__ b0,
           const float* __restrict__ bh,
           const float* __restrict__ Wout,
           const float* __restrict__ bout,
           float* __restrict__ out) {
    extern __shared__ char smem[];
    const uint32_t sb = smem_u32(smem);
    const int tid  = threadIdx.x;
    const int wid  = tid >> 5;
    const int lane = tid & 31;
    const int q    = lane & 3;

    // ---- prefetch ALL 7 layer images (once per CTA, ever) ----
    #pragma unroll
    for (int l = 0; l < NHID; l++) {
        const char* src = (const char*)&g_wimg[l][0];
        uint32_t dst = sb + SM_WBUF + (uint32_t)l * 32768;
        #pragma unroll
        for (int i = 0; i < 8; i++)
            CP_ASYNC16(dst + (uint32_t)(tid + i * THREADS) * 16,
                       src + (size_t)(tid + i * THREADS) * 16);
        CP_COMMIT();
    }

    // ---- stage f16x2 biases + Wout frag stream ----
    {
        uint32_t* b2s = (uint32_t*)(smem + SM_BIASH);
        for (int i = tid; i < NHID * 64; i += THREADS)
            b2s[i] = pack_f16(bh[2 * i], bh[2 * i + 1]);
        if (tid < 192)
            ((uint32_t*)(smem + SM_WOUTF))[tid] = g_woutfrag[tid];
    }

    // per-thread ldmatrix address pieces
    const uint32_t nloc = (uint32_t)((lane & 7) + ((lane >> 4) & 1) * 8);
    const uint32_t jbit = (uint32_t)((lane >> 3) & 1);
    uint32_t swz[8];
    #pragma unroll
    for (int s = 0; s < 8; s++)
        swz[s] = nloc * 256 + ((((uint32_t)(2 * s) + jbit) ^ (nloc & 7)) << 4);

    const uint32_t* b2base = (const uint32_t*)(smem + SM_BIASH);
    const uint32_t* wf = (const uint32_t*)(smem + SM_WOUTF);

    // final-projection bias pattern (cols 2q, 2q+1 of [bout0,bout1,bout2,0])
    float bfx = 0.f, bfy = 0.f;
    if (q == 0) { bfx = bout[0]; bfy = bout[1]; }
    else if (q == 1) { bfx = bout[2]; }

    // ---- THE ONLY BARRIER in the entire kernel ----
    CP_WAIT(0);
    __syncthreads();

    uint32_t A0a[8][4], A0b[8][4], A1a[8][4], A1b[8][4];

    // x fragments for the first tile (padded rows [x0,x1,x2,1,0..0])
    uint32_t xf[4];
    {
        const int r = blockIdx.x * TILE_ROWS + wid * 32 + (lane >> 2);
        const float* xp = x + (size_t)r * 3;
        #pragma unroll
        for (int j = 0; j < 4; j++)
            xf[j] = xfrag(xp[24 * j + 0], xp[24 * j + 1], xp[24 * j + 2], q);
    }

    // ================= persistent tile loop, zero synchronization ==========
    #pragma unroll 1
    for (int tile = blockIdx.x; tile < NTILES; tile += NCTAS) {
        const int rbase = tile * TILE_ROWS + wid * 32 + (lane >> 2);
        const int g0 = rbase, g1 = rbase + 8, g2 = rbase + 16, g3 = rbase + 24;

        // ---- layer 0 via m16n8k8 MMA: h1 = relu(x @ [W0|b0]^T) ----
        #pragma unroll
        for (int c = 0; c < 16; c++) {
            const uint32_t bw = __ldg(&g_w0frag[c * 32 + lane]);
            float Cfa[4], Cfb[4];
            MMA16808_INIT(Cfa, xf[0], xf[1], bw, 0.f, 0.f);
            MMA16808_INIT(Cfb, xf[2], xf[3], bw, 0.f, 0.f);
            const int s = c >> 1, off = (c & 1) * 2;
            A0a[s][off]     = epi_op2(Cfa[0], Cfa[1]);
            A0a[s][off + 1] = epi_op2(Cfa[2], Cfa[3]);
            A0b[s][off]     = epi_op2(Cfb[0], Cfb[1]);
            A0b[s][off + 1] = epi_op2(Cfb[2], Cfb[3]);
        }

        // ---- prefetch next tile's x (latency hidden behind 7 MMA layers) ----
        {
            const int ntile = tile + NCTAS;
            if (ntile < NTILES) {
                const int r = ntile * TILE_ROWS + wid * 32 + (lane >> 2);
                const float* xp = x + (size_t)r * 3;
                #pragma unroll
                for (int j = 0; j < 4; j++)
                    xf[j] = xfrag(xp[24 * j + 0], xp[24 * j + 1], xp[24 * j + 2], q);
            }
        }

        // ---- 6 hidden layers, no syncs ----
        #pragma unroll 1
        for (int it = 0; it < 3; it++) {
            const int l0 = 2 * it;
            hidden_layer(sb + SM_WBUF + (uint32_t)l0 * 32768, swz, q,
                         A0a, A0b, A1a, A1b, b2base + l0 * 64);
            hidden_layer(sb + SM_WBUF + (uint32_t)(l0 + 1) * 32768, swz, q,
                         A1a, A1b, A0a, A0b, b2base + (l0 + 1) * 64);
        }
        // ---- hidden layer 6 (A0 -> A1 = relu(h7) fp16 frags) ----
        hidden_layer(sb + SM_WBUF + 6u * 32768, swz, q,
                     A0a, A0b, A1a, A1b, b2base + 6 * 64);

        // ---- final [128 -> 3] projection via m16n8k8 MMAs ----
        {
            float Cfa[4], Cfb[4];
            {
                const uint32_t bw = (lane < 12) ? wf[lane] : 0u;
                MMA16808_INIT(Cfa, A1a[0][0], A1a[0][1], bw, bfx, bfy);
                MMA16808_INIT(Cfb, A1b[0][0], A1b[0][1], bw, bfx, bfy);
            }
            #pragma unroll
            for (int c = 1; c < 16; c++) {
                const uint32_t bw = (lane < 12) ? wf[c * 12 + lane] : 0u;
                const int s = c >> 1, off = (c & 1) * 2;
                MMA16808(Cfa, A1a[s][off], A1a[s][off + 1], bw);
                MMA16808(Cfb, A1b[s][off], A1b[s][off + 1], bw);
            }
            if (q == 0) {
                out[g0 * 3 + 0] = Cfa[0]; out[g0 * 3 + 1] = Cfa[1];
                out[g1 * 3 + 0] = Cfa[2]; out[g1 * 3 + 1] = Cfa[3];
                out[g2 * 3 + 0] = Cfb[0]; out[g2 * 3 + 1] = Cfb[1];
                out[g3 * 3 + 0] = Cfb[2]; out[g3 * 3 + 1] = Cfb[3];
            } else if (q == 1) {
                out[g0 * 3 + 2] = Cfa[0]; out[g1 * 3 + 2] = Cfa[2];
                out[g2 * 3 + 2] = Cfb[0]; out[g3 * 3 + 2] = Cfb[2];
            }
        }
    }
}

// ---------------------------------------------------------------------------
// kernel_launch
// ---------------------------------------------------------------------------
extern "C" void kernel_launch(void* const* d_in, const int* in_sizes, int n_in,
                              void* d_out, int out_size) {
    const float* x    = (const float*)d_in[0];   // [262144,3]
    const float* W0   = (const float*)d_in[1];   // [128,3]
    const float* b0   = (const float*)d_in[2];   // [128]
    const float* Wh   = (const float*)d_in[3];   // [7,128,128]
    const float* bh   = (const float*)d_in[4];   // [7,128]
    const float* Wout = (const float*)d_in[5];   // [3,128]
    const float* bout = (const float*)d_in[6];   // [3]
    float* out = (float*)d_out;                  // [262144,3]

    static bool attr_set = false;
    if (!attr_set) {
        cudaFuncSetAttribute(mlp_kernel,
                             cudaFuncAttributeMaxDynamicSharedMemorySize, SMEM_SZ);
        attr_set = true;
    }

    prep_weights_kernel<<<(NHID * 128 * 128 + 255) / 256, 256>>>(Wh);
    prep_small_kernel<<<1, 512>>>(Wout, W0, b0);
    mlp_kernel<<<NCTAS, THREADS, SMEM_SZ>>>(x, W0, b0, bh, Wout, bout, out);
}

// round 17
// speedup vs baseline: 1.1355x; 1.0610x over previous
#include <cuda_runtime.h>
#include <cuda_fp16.h>
#include <cstdint>

// ============================================================================
// NSFPRawMLP: x[262144,3] -> 128 -> (7x 128x128 + ReLU) -> 3
// R17: R16 persistent base + FP16 ACCUMULATORS in layer 0 and all hidden
// layers (m16n8k16.f16 / m16n8k8.f16). Accumulator output is already packed
// f16x2 in A-fragment layout: epilogue = one hmax2 per fragment. Bias rides
// in the accumulator init. Final 128->3 projection stays fp32-accum.
// ============================================================================

#define NROWS    262144
#define NHID     7
#define TILE_ROWS 256
#define NTILES   (NROWS / TILE_ROWS)     // 1024 tiles
#define NCTAS    148                     // persistent: one per SM
#define THREADS  256                     // 8 warps, 32 rows/warp

// Weight images: [layer][32768 B] fp16.
// byte = n*256 + ((chunk ^ (n&7))<<4) + (k&7)*2, chunk = k>>3  (XOR swizzle)
static __device__ __align__(128) unsigned char g_wimg[NHID][32768];
// Wout fragment stream for m16n8k8: [16 k8-chunks][12 lanes] packed f16x2
static __device__ uint32_t g_woutfrag[192];
// [W0 | b0] fragment table for layer-0 m16n8k8: [16 n-tiles][32 lanes]
static __device__ uint32_t g_w0frag[512];

// ---------------------------------------------------------------------------
// SMEM layout
// ---------------------------------------------------------------------------
#define SM_WBUF    0                     // 7 x 32768 = 229376
#define SM_BIASH   229376                // 7*64 half2 = 1792
#define SM_WOUTF   231168                // 192 words = 768
#define SMEM_SZ    231936

// ---------------------------------------------------------------------------
// PTX helpers (base-target, sm_80+)
// ---------------------------------------------------------------------------
__device__ __forceinline__ uint32_t smem_u32(const void* p) {
    uint32_t a;
    asm("{ .reg .u64 t; cvta.to.shared.u64 t, %1; cvt.u32.u64 %0, t; }"
        : "=r"(a) : "l"(p));
    return a;
}

#define CP_ASYNC16(dst_u32, src_ptr) \
    asm volatile("cp.async.cg.shared.global [%0], [%1], 16;" \
                 :: "r"(dst_u32), "l"(src_ptr) : "memory")
#define CP_COMMIT() asm volatile("cp.async.commit_group;" ::: "memory")
#define CP_WAIT(n)  asm volatile("cp.async.wait_group %0;" :: "n"(n) : "memory")

#define LDSM4(r0, r1, r2, r3, addr) \
    asm volatile("ldmatrix.sync.aligned.m8n8.x4.shared.b16 {%0,%1,%2,%3}, [%4];" \
                 : "=r"(r0), "=r"(r1), "=r"(r2), "=r"(r3) : "r"(addr))

// fp16-accumulate MMA: C2 (2 regs, packed f16x2) += A * B
#define MMA16816H(C2, A, b0_, b1_) \
    asm volatile("mma.sync.aligned.m16n8k16.row.col.f16.f16.f16.f16 " \
                 "{%0,%1},{%2,%3,%4,%5},{%6,%7},{%0,%1};" \
                 : "+r"((C2)[0]), "+r"((C2)[1]) \
                 : "r"((A)[0]), "r"((A)[1]), "r"((A)[2]), "r"((A)[3]), \
                   "r"(b0_), "r"(b1_))

// fp16-accumulate MMA with bias init: C2 = A * B + {bb, bb}
#define MMA16816H_INIT(C2, A, b0_, b1_, bb) \
    asm volatile("mma.sync.aligned.m16n8k16.row.col.f16.f16.f16.f16 " \
                 "{%0,%1},{%2,%3,%4,%5},{%6,%7},{%8,%8};" \
                 : "=r"((C2)[0]), "=r"((C2)[1]) \
                 : "r"((A)[0]), "r"((A)[1]), "r"((A)[2]), "r"((A)[3]), \
                   "r"(b0_), "r"(b1_), "r"(bb))

// fp16-accumulate k8 MMA with zero init (layer 0; bias embedded in B table)
#define MMA16808H_Z(C2, a0_, a1_, b_) \
    asm volatile("mma.sync.aligned.m16n8k8.row.col.f16.f16.f16.f16 " \
                 "{%0,%1},{%2,%3},{%4},{%5,%5};" \
                 : "=r"((C2)[0]), "=r"((C2)[1]) \
                 : "r"(a0_), "r"(a1_), "r"(b_), "r"(0u))

// fp32-accumulate k8 MMA (final projection)
#define MMA16808(C, a0_, a1_, b_) \
    asm volatile("mma.sync.aligned.m16n8k8.row.col.f32.f16.f16.f32 " \
                 "{%0,%1,%2,%3},{%4,%5},{%6},{%0,%1,%2,%3};" \
                 : "+f"((C)[0]), "+f"((C)[1]), "+f"((C)[2]), "+f"((C)[3]) \
                 : "r"(a0_), "r"(a1_), "r"(b_))

#define MMA16808_INIT(C, a0_, a1_, b_, bx, by) \
    asm volatile("mma.sync.aligned.m16n8k8.row.col.f32.f16.f16.f32 " \
                 "{%0,%1,%2,%3},{%4,%5},{%6},{%7,%8,%7,%8};" \
                 : "=f"((C)[0]), "=f"((C)[1]), "=f"((C)[2]), "=f"((C)[3]) \
                 : "r"(a0_), "r"(a1_), "r"(b_), "f"(bx), "f"(by))

// pack two fp32 -> fp16x2 (round-to-nearest)
__device__ __forceinline__ uint32_t pack_f16(float v0, float v1) {
    uint32_t r;
    asm("cvt.rn.f16x2.f32 %0, %1, %2;" : "=r"(r) : "f"(v1), "f"(v0));
    return r;
}

// relu on packed f16x2
__device__ __forceinline__ uint32_t relu2(uint32_t v) {
    const __half2 z = __floats2half2_rn(0.f, 0.f);
    __half2 r = __hmax2(*reinterpret_cast<__half2*>(&v), z);
    return *reinterpret_cast<uint32_t*>(&r);
}

// layer-0 x fragment: padded row [x0,x1,x2,1,0,0,0,0], cols 2q,2q+1
__device__ __forceinline__ uint32_t xfrag(float x0, float x1, float x2, int q) {
    float u0 = (q == 0) ? x0 : (q == 1 ? x2 : 0.f);
    float u1 = (q == 0) ? x1 : (q == 1 ? 1.0f : 0.f);
    return pack_f16(u0, u1);
}

// ---------------------------------------------------------------------------
// Prep kernels
// ---------------------------------------------------------------------------
__global__ void prep_weights_kernel(const float* __restrict__ Wh) {
    int idx = blockIdx.x * blockDim.x + threadIdx.x;
    if (idx >= NHID * 128 * 128) return;
    int l = idx >> 14;
    int n = (idx >> 7) & 127;
    int k = idx & 127;
    __half w = __float2half_rn(Wh[idx]);
    uint32_t chunk = (uint32_t)k >> 3;
    uint32_t off = (uint32_t)n * 256 + ((chunk ^ ((uint32_t)n & 7)) << 4)
                 + ((uint32_t)k & 7) * 2;
    *(__half*)&g_wimg[l][off] = w;
}

// Wout frag stream + [W0|b0] frag table
__global__ void prep_small_kernel(const float* __restrict__ Wout,
                                  const float* __restrict__ W0,
                                  const float* __restrict__ b0) {
    int idx = threadIdx.x;
    if (idx < 192) {
        int c = idx / 12, l = idx % 12;
        int n = l >> 2, qq = l & 3;
        int k0 = 8 * c + 2 * qq;
        g_woutfrag[idx] = pack_f16(Wout[n * 128 + k0], Wout[n * 128 + k0 + 1]);
    }
    if (idx < 512) {
        int c = idx >> 5, l = idx & 31;
        int n = c * 8 + (l >> 2);
        int qq = l & 3;
        int k0 = 2 * qq, k1 = 2 * qq + 1;
        float v0 = (k0 < 3) ? W0[n * 3 + k0] : ((k0 == 3) ? b0[n] : 0.f);
        float v1 = (k1 < 3) ? W0[n * 3 + k1] : ((k1 == 3) ? b0[n] : 0.f);
        g_w0frag[idx] = pack_f16(v0, v1);
    }
}

// ---------------------------------------------------------------------------
// One hidden layer, fp16 accumulators. pp-outer k-loop, bias in MMA init,
// per-block 1-op epilogue (hmax2) overlapped. No syncs.
// b2: f16x2 bias pairs for this layer (smem), indexed by col-pair = 4*tile+q.
// ---------------------------------------------------------------------------
__device__ __forceinline__ void hidden_layer(
    uint32_t wb, const uint32_t (&swz)[8], int q,
    uint32_t (&Aia)[8][4], uint32_t (&Aib)[8][4],
    uint32_t (&Aoa)[8][4], uint32_t (&Aob)[8][4],
    const uint32_t* __restrict__ b2) {
    uint32_t Ca[16][2], Cb[16][2];
    uint32_t h[2][8];
    LDSM4(h[0][0], h[0][1], h[0][2], h[0][3], wb + swz[0]);
    LDSM4(h[0][4], h[0][5], h[0][6], h[0][7], wb + swz[0] + 4096);
    #pragma unroll
    for (int grp = 0; grp < 32; grp++) {
        const int cur = grp & 1, nxt = cur ^ 1;
        const int pp = grp >> 3, s = grp & 7;
        if (grp + 1 < 32) {
            const int pp1 = (grp + 1) >> 3, s1 = (grp + 1) & 7;
            const uint32_t a0 = wb + swz[s1] + (uint32_t)(2 * pp1) * 4096;
            LDSM4(h[nxt][0], h[nxt][1], h[nxt][2], h[nxt][3], a0);
            LDSM4(h[nxt][4], h[nxt][5], h[nxt][6], h[nxt][7], a0 + 4096);
        }
        if (s == 0) {
            // first k-step: C = A*B + bias (f16, broadcast to both row frags)
            const uint32_t bb0 = b2[16 * pp + q];
            const uint32_t bb1 = b2[16 * pp + 4 + q];
            const uint32_t bb2 = b2[16 * pp + 8 + q];
            const uint32_t bb3 = b2[16 * pp + 12 + q];
            MMA16816H_INIT(Ca[4 * pp + 0], Aia[0], h[cur][0], h[cur][1], bb0);
            MMA16816H_INIT(Cb[4 * pp + 0], Aib[0], h[cur][0], h[cur][1], bb0);
            MMA16816H_INIT(Ca[4 * pp + 1], Aia[0], h[cur][2], h[cur][3], bb1);
            MMA16816H_INIT(Cb[4 * pp + 1], Aib[0], h[cur][2], h[cur][3], bb1);
            MMA16816H_INIT(Ca[4 * pp + 2], Aia[0], h[cur][4], h[cur][5], bb2);
            MMA16816H_INIT(Cb[4 * pp + 2], Aib[0], h[cur][4], h[cur][5], bb2);
            MMA16816H_INIT(Ca[4 * pp + 3], Aia[0], h[cur][6], h[cur][7], bb3);
            MMA16816H_INIT(Cb[4 * pp + 3], Aib[0], h[cur][6], h[cur][7], bb3);
        } else {
            MMA16816H(Ca[4 * pp + 0], Aia[s], h[cur][0], h[cur][1]);
            MMA16816H(Cb[4 * pp + 0], Aib[s], h[cur][0], h[cur][1]);
            MMA16816H(Ca[4 * pp + 1], Aia[s], h[cur][2], h[cur][3]);
            MMA16816H(Cb[4 * pp + 1], Aib[s], h[cur][2], h[cur][3]);
            MMA16816H(Ca[4 * pp + 2], Aia[s], h[cur][4], h[cur][5]);
            MMA16816H(Cb[4 * pp + 2], Aib[s], h[cur][4], h[cur][5]);
            MMA16816H(Ca[4 * pp + 3], Aia[s], h[cur][6], h[cur][7]);
            MMA16816H(Cb[4 * pp + 3], Aib[s], h[cur][6], h[cur][7]);
        }
        // previous block's epilogue: relu only (bias already in C, already f16)
        if (s == 1 && pp > 0) {
            const int p0 = pp - 1;
            #pragma unroll
            for (int e = 0; e < 2; e++) {
                const int sg = 2 * p0 + e;
                Aoa[sg][0] = relu2(Ca[2 * sg][0]);
                Aoa[sg][1] = relu2(Ca[2 * sg][1]);
                Aoa[sg][2] = relu2(Ca[2 * sg + 1][0]);
                Aoa[sg][3] = relu2(Ca[2 * sg + 1][1]);
                Aob[sg][0] = relu2(Cb[2 * sg][0]);
                Aob[sg][1] = relu2(Cb[2 * sg][1]);
                Aob[sg][2] = relu2(Cb[2 * sg + 1][0]);
                Aob[sg][3] = relu2(Cb[2 * sg + 1][1]);
            }
        }
    }
    #pragma unroll
    for (int e = 0; e < 2; e++) {
        const int sg = 6 + e;
        Aoa[sg][0] = relu2(Ca[2 * sg][0]);
        Aoa[sg][1] = relu2(Ca[2 * sg][1]);
        Aoa[sg][2] = relu2(Ca[2 * sg + 1][0]);
        Aoa[sg][3] = relu2(Ca[2 * sg + 1][1]);
        Aob[sg][0] = relu2(Cb[2 * sg][0]);
        Aob[sg][1] = relu2(Cb[2 * sg][1]);
        Aob[sg][2] = relu2(Cb[2 * sg + 1][0]);
        Aob[sg][3] = relu2(Cb[2 * sg + 1][1]);
    }
}

// ---------------------------------------------------------------------------
// Main kernel: PERSISTENT. 148 CTAs, 8 warps each, tile-strided over 1024
// tiles of 256 rows. One barrier total; zero syncs in the tile loop.
// ---------------------------------------------------------------------------
__global__ void __launch_bounds__(THREADS, 1)
mlp_kernel(const float* __restrict__ x,
           const float* __restrict__ W0,
           const float* __restrict__ b0,
           const float* __restrict__ bh,
           const float* __restrict__ Wout,
           const float* __restrict__ bout,
           float* __restrict__ out) {
    extern __shared__ char smem[];
    const uint32_t sb = smem_u32(smem);
    const int tid  = threadIdx.x;
    const int wid  = tid >> 5;
    const int lane = tid & 31;
    const int q    = lane & 3;

    // ---- prefetch ALL 7 layer images (once per CTA, ever) ----
    #pragma unroll
    for (int l = 0; l < NHID; l++) {
        const char* src = (const char*)&g_wimg[l][0];
        uint32_t dst = sb + SM_WBUF + (uint32_t)l * 32768;
        #pragma unroll
        for (int i = 0; i < 8; i++)
            CP_ASYNC16(dst + (uint32_t)(tid + i * THREADS) * 16,
                       src + (size_t)(tid + i * THREADS) * 16);
        CP_COMMIT();
    }

    // ---- stage f16x2 biases + Wout frag stream ----
    {
        uint32_t* b2s = (uint32_t*)(smem + SM_BIASH);
        for (int i = tid; i < NHID * 64; i += THREADS)
            b2s[i] = pack_f16(bh[2 * i], bh[2 * i + 1]);
        if (tid < 192)
            ((uint32_t*)(smem + SM_WOUTF))[tid] = g_woutfrag[tid];
    }

    // per-thread ldmatrix address pieces
    const uint32_t nloc = (uint32_t)((lane & 7) + ((lane >> 4) & 1) * 8);
    const uint32_t jbit = (uint32_t)((lane >> 3) & 1);
    uint32_t swz[8];
    #pragma unroll
    for (int s = 0; s < 8; s++)
        swz[s] = nloc * 256 + ((((uint32_t)(2 * s) + jbit) ^ (nloc & 7)) << 4);

    const uint32_t* b2base = (const uint32_t*)(smem + SM_BIASH);
    const uint32_t* wf = (const uint32_t*)(smem + SM_WOUTF);

    // final-projection bias pattern (cols 2q, 2q+1 of [bout0,bout1,bout2,0])
    float bfx = 0.f, bfy = 0.f;
    if (q == 0) { bfx = bout[0]; bfy = bout[1]; }
    else if (q == 1) { bfx = bout[2]; }

    // ---- THE ONLY BARRIER in the entire kernel ----
    CP_WAIT(0);
    __syncthreads();

    uint32_t A0a[8][4], A0b[8][4], A1a[8][4], A1b[8][4];

    // x fragments for the first tile (padded rows [x0,x1,x2,1,0..0])
    uint32_t xf[4];
    {
        const int r = blockIdx.x * TILE_ROWS + wid * 32 + (lane >> 2);
        const float* xp = x + (size_t)r * 3;
        #pragma unroll
        for (int j = 0; j < 4; j++)
            xf[j] = xfrag(xp[24 * j + 0], xp[24 * j + 1], xp[24 * j + 2], q);
    }

    // ================= persistent tile loop, zero synchronization ==========
    #pragma unroll 1
    for (int tile = blockIdx.x; tile < NTILES; tile += NCTAS) {
        const int rbase = tile * TILE_ROWS + wid * 32 + (lane >> 2);
        const int g0 = rbase, g1 = rbase + 8, g2 = rbase + 16, g3 = rbase + 24;

        // ---- layer 0 via m16n8k8 f16-accum MMA: h1 = relu(x @ [W0|b0]^T) ----
        #pragma unroll
        for (int c = 0; c < 16; c++) {
            const uint32_t bw = __ldg(&g_w0frag[c * 32 + lane]);
            uint32_t Cfa[2], Cfb[2];
            MMA16808H_Z(Cfa, xf[0], xf[1], bw);
            MMA16808H_Z(Cfb, xf[2], xf[3], bw);
            const int s = c >> 1, off = (c & 1) * 2;
            A0a[s][off]     = relu2(Cfa[0]);
            A0a[s][off + 1] = relu2(Cfa[1]);
            A0b[s][off]     = relu2(Cfb[0]);
            A0b[s][off + 1] = relu2(Cfb[1]);
        }

        // ---- prefetch next tile's x (latency hidden behind 7 MMA layers) ----
        {
            const int ntile = tile + NCTAS;
            if (ntile < NTILES) {
                const int r = ntile * TILE_ROWS + wid * 32 + (lane >> 2);
                const float* xp = x + (size_t)r * 3;
                #pragma unroll
                for (int j = 0; j < 4; j++)
                    xf[j] = xfrag(xp[24 * j + 0], xp[24 * j + 1], xp[24 * j + 2], q);
            }
        }

        // ---- 6 hidden layers, no syncs ----
        #pragma unroll 1
        for (int it = 0; it < 3; it++) {
            const int l0 = 2 * it;
            hidden_layer(sb + SM_WBUF + (uint32_t)l0 * 32768, swz, q,
                         A0a, A0b, A1a, A1b, b2base + l0 * 64);
            hidden_layer(sb + SM_WBUF + (uint32_t)(l0 + 1) * 32768, swz, q,
                         A1a, A1b, A0a, A0b, b2base + (l0 + 1) * 64);
        }
        // ---- hidden layer 6 (A0 -> A1 = relu(h7) fp16 frags) ----
        hidden_layer(sb + SM_WBUF + 6u * 32768, swz, q,
                     A0a, A0b, A1a, A1b, b2base + 6 * 64);

        // ---- final [128 -> 3] projection via m16n8k8 fp32-accum MMAs ----
        {
            float Cfa[4], Cfb[4];
            {
                const uint32_t bw = (lane < 12) ? wf[lane] : 0u;
                MMA16808_INIT(Cfa, A1a[0][0], A1a[0][1], bw, bfx, bfy);
                MMA16808_INIT(Cfb, A1b[0][0], A1b[0][1], bw, bfx, bfy);
            }
            #pragma unroll
            for (int c = 1; c < 16; c++) {
                const uint32_t bw = (lane < 12) ? wf[c * 12 + lane] : 0u;
                const int s = c >> 1, off = (c & 1) * 2;
                MMA16808(Cfa, A1a[s][off], A1a[s][off + 1], bw);
                MMA16808(Cfb, A1b[s][off], A1b[s][off + 1], bw);
            }
            if (q == 0) {
                out[g0 * 3 + 0] = Cfa[0]; out[g0 * 3 + 1] = Cfa[1];
                out[g1 * 3 + 0] = Cfa[2]; out[g1 * 3 + 1] = Cfa[3];
                out[g2 * 3 + 0] = Cfb[0]; out[g2 * 3 + 1] = Cfb[1];
                out[g3 * 3 + 0] = Cfb[2]; out[g3 * 3 + 1] = Cfb[3];
            } else if (q == 1) {
                out[g0 * 3 + 2] = Cfa[0]; out[g1 * 3 + 2] = Cfa[2];
                out[g2 * 3 + 2] = Cfb[0]; out[g3 * 3 + 2] = Cfb[2];
            }
        }
    }
}

// ---------------------------------------------------------------------------
// kernel_launch
// ---------------------------------------------------------------------------
extern "C" void kernel_launch(void* const* d_in, const int* in_sizes, int n_in,
                              void* d_out, int out_size) {
    const float* x    = (const float*)d_in[0];   // [262144,3]
    const float* W0   = (const float*)d_in[1];   // [128,3]
    const float* b0   = (const float*)d_in[2];   // [128]
    const float* Wh   = (const float*)d_in[3];   // [7,128,128]
    const float* bh   = (const float*)d_in[4];   // [7,128]
    const float* Wout = (const float*)d_in[5];   // [3,128]
    const float* bout = (const float*)d_in[6];   // [3]
    float* out = (float*)d_out;                  // [262144,3]

    static bool attr_set = false;
    if (!attr_set) {
        cudaFuncSetAttribute(mlp_kernel,
                             cudaFuncAttributeMaxDynamicSharedMemorySize, SMEM_SZ);
        attr_set = true;
    }

    prep_weights_kernel<<<(NHID * 128 * 128 + 255) / 256, 256>>>(Wh);
    prep_small_kernel<<<1, 512>>>(Wout, W0, b0);
    mlp_kernel<<<NCTAS, THREADS, SMEM_SZ>>>(x, W0, b0, bh, Wout, bout, out);
}